// round 7
// baseline (speedup 1.0000x reference)
#include <cuda_runtime.h>

// Problem shape (fixed by the dataset reference)
#define BB      16
#define TT      256
#define NPTS    2048
#define NF      (NPTS * 3)             // 6144 flat (point,coord) indices
#define TCHUNK  64
#define NCHUNKS (TT / TCHUNK)          // 4
#define BC      (BB * NCHUNKS)         // 64 partial groups
#define THREADS 256
#define CPB     (NF / THREADS)         // 24 CTAs per bc group
#define NCTA    (BC * CPB)             // 1536 main CTAs
#define RFIN    128                    // finish CTAs
#define PTSPC   (NPTS / RFIN)          // 16 points per finish CTA
#define FLATSPC (PTSPC * 3)            // 48 flats per finish CTA
#define NGRP    8                      // bc groups in finish stage A
#define BCG     (BC / NGRP)            // 8 bc per group

// Partial per-(n,c) stats: g_part[bc][stat][flat], stat: 0 sxp, 1 ssp, 2 sxg, 3 ssg, 4 cnt
__device__ float  g_part[BC * 5 * NF];      // 7.9 MB, fully overwritten each replay
__device__ float4 g_pscal[NCTA];            // per-CTA: cnt3x, recon, vels, velc3x
__device__ float  g_fin[RFIN * 5];          // per-finish-CTA: id, cnt3x, recon, vels, velc3x
__device__ unsigned g_ctr;                  // last-block counter (self-resetting)

__global__ __launch_bounds__(THREADS) void main_k(
    const float* __restrict__ pred,
    const float* __restrict__ gt,
    const float* __restrict__ vis)
{
    const int bc    = blockIdx.x / CPB;
    const int sub   = blockIdx.x - bc * CPB;
    const int flat  = sub * THREADS + threadIdx.x;
    const int chunk = bc & (NCHUNKS - 1);
    const int b     = bc >> 2;                 // NCHUNKS = 4
    const int t0    = chunk * TCHUNK;

    const int   n = flat / 3;
    const int   c = flat - 3 * n;
    const float w = (c == 2) ? 2.f : 1.f;

    const int row0 = b * TT + t0;
    const float* pp = pred + (long)row0 * NF + flat;
    const float* gp = gt   + (long)row0 * NF + flat;
    const float* vp = vis  + (long)row0 * NPTS + n;

    float sxp = 0.f, ssp = 0.f, sxg = 0.f, ssg = 0.f, cnt = 0.f;
    float recon = 0.f, vels = 0.f, velc = 0.f;

    float pd = 0.f, pm = 0.f;
    if (t0 > 0) {
        pm = (vp[-NPTS] > 0.5f) ? 1.f : 0.f;
        pd = pp[-NF] - gp[-NF];
    }

#pragma unroll 4
    for (int t = 0; t < TCHUNK; ++t) {
        float m = (vp[0] > 0.5f) ? 1.f : 0.f;
        float p = pp[0];
        float g = gp[0];
        pp += NF; gp += NF; vp += NPTS;

        float d = p - g;
        recon += w * (m * d) * d;
        cnt   += m;

        float mp = m * p, mg = m * g;
        sxp += mp;  ssp += mp * p;
        sxg += mg;  ssg += mg * g;

        float vm = m * pm;
        float tv = d - pd;
        vels += (vm * tv) * tv;
        velc += vm;

        pd = d; pm = m;
    }

    // per-(n,c) stats -> partial buffer (coalesced scalar stores, no atomics)
    {
        float* out = &g_part[(long)bc * 5 * NF + flat];
        out[0 * NF] = sxp;
        out[1 * NF] = ssp;
        out[2 * NF] = sxg;
        out[3 * NF] = ssg;
        out[4 * NF] = cnt;
    }

    // scalar partials: warp reduce -> smem -> one float4 store per CTA
    const unsigned fmask = 0xffffffffu;
    __shared__ float swarp[8][4];
#pragma unroll
    for (int o = 16; o > 0; o >>= 1) {
        cnt   += __shfl_down_sync(fmask, cnt,   o);
        recon += __shfl_down_sync(fmask, recon, o);
        vels  += __shfl_down_sync(fmask, vels,  o);
        velc  += __shfl_down_sync(fmask, velc,  o);
    }
    int wd = threadIdx.x >> 5;
    if ((threadIdx.x & 31) == 0) {
        swarp[wd][0] = cnt; swarp[wd][1] = recon; swarp[wd][2] = vels; swarp[wd][3] = velc;
    }
    __syncthreads();
    if (threadIdx.x == 0) {
        float s0 = 0.f, s1 = 0.f, s2 = 0.f, s3 = 0.f;
#pragma unroll
        for (int i = 0; i < 8; ++i) {
            s0 += swarp[i][0]; s1 += swarp[i][1]; s2 += swarp[i][2]; s3 += swarp[i][3];
        }
        g_pscal[blockIdx.x] = make_float4(s0, s1, s2, s3);
    }
}

// Fused finish: float4 group-split reduce of partials, identity, scalar fold,
// last block combines and writes the 4 outputs.
__global__ __launch_bounds__(512) void finish_k(float* __restrict__ out)
{
    const int t  = threadIdx.x;
    const int bx = blockIdx.x;
    const int f0 = bx * FLATSPC;

    // sgrp[grp][stat][48 floats] ; written as float4 per (stat,col)
    __shared__ float sgrp[NGRP][5][FLATSPC];
    __shared__ float scomb[5][FLATSPC];
    __shared__ float part5[5];
    __shared__ bool  islast;

    // Stage A: t -> grp = t/64, pair = t%64 (60 valid: stat = pair/12, col = pair%12)
    {
        int grp  = t >> 6;
        int pair = t & 63;
        if (pair < 60) {
            int stat = pair / 12;
            int col  = pair - stat * 12;
            const float* base = g_part + (long)(grp * BCG) * 5 * NF
                                       + (long)stat * NF + f0 + col * 4;
            float4 s = make_float4(0.f, 0.f, 0.f, 0.f);
#pragma unroll
            for (int i = 0; i < BCG; ++i) {
                float4 v = *(const float4*)(base + (long)i * 5 * NF);
                s.x += v.x; s.y += v.y; s.z += v.z; s.w += v.w;
            }
            *(float4*)&sgrp[grp][stat][col * 4] = s;
        }
    }
    __syncthreads();

    // Stage B1: combine groups (threads 0..239), Stage C: scalar fold (threads 256..287)
    if (t < 5 * FLATSPC) {
        int stat = t / FLATSPC;
        int fo   = t - stat * FLATSPC;
        float s = 0.f;
#pragma unroll
        for (int g = 0; g < NGRP; ++g)
            s += sgrp[g][stat][fo];
        scomb[stat][fo] = s;
    }
    if (t >= 256 && t < 288) {
        int lane = t - 256;                         // entries 0..11 valid
        float4 v = make_float4(0.f, 0.f, 0.f, 0.f);
        if (lane < NCTA / RFIN)                     // 12 main CTAs per finish CTA
            v = g_pscal[bx * (NCTA / RFIN) + lane];
#pragma unroll
        for (int o = 16; o > 0; o >>= 1) {
            v.x += __shfl_down_sync(0xffffffffu, v.x, o);
            v.y += __shfl_down_sync(0xffffffffu, v.y, o);
            v.z += __shfl_down_sync(0xffffffffu, v.z, o);
            v.w += __shfl_down_sync(0xffffffffu, v.w, o);
        }
        if (lane == 0) {
            part5[1] = v.x; part5[2] = v.y; part5[3] = v.z; part5[4] = v.w;
        }
    }
    __syncthreads();

    // Stage B2: identity for this CTA's 16 points (warp 0)
    float idp = 0.f;
    if (t < PTSPC) {
        int fo = t * 3;
        float cn = scomb[4][fo];
        if (cn > 1.f) {
            float inv_n  = 1.f / cn;
            float inv_n1 = 1.f / (cn - 1.f);
            float adsum = 0.f, vgsum = 0.f;
#pragma unroll
            for (int k = 0; k < 3; ++k) {
                float sp  = scomb[0][fo + k];
                float ssp = scomb[1][fo + k];
                float sg  = scomb[2][fo + k];
                float ssg = scomb[3][fo + k];
                float vp = (ssp - sp * sp * inv_n) * inv_n1;
                float vg = (ssg - sg * sg * inv_n) * inv_n1;
                adsum += fabsf(vp - vg);
                vgsum += vg;
            }
            idp = adsum / (vgsum + 1e-6f);
        }
    }
    if (t < 32) {
#pragma unroll
        for (int o = 16; o > 0; o >>= 1)
            idp += __shfl_down_sync(0xffffffffu, idp, o);
        if (t == 0) part5[0] = idp;
    }
    __syncthreads();

    if (t < 5) g_fin[bx * 5 + t] = part5[t];
    __threadfence();
    if (t == 0) {
        unsigned old = atomicAdd(&g_ctr, 1u);
        islast = (old == RFIN - 1);
    }
    __syncthreads();

    if (islast) {
        __threadfence();
        __shared__ float red[5][RFIN];
        if (t < RFIN) {                    // only t<128 touches red[]
            const float* f = &g_fin[t * 5];
            red[0][t] = __ldcg(f + 0);
            red[1][t] = __ldcg(f + 1);
            red[2][t] = __ldcg(f + 2);
            red[3][t] = __ldcg(f + 3);
            red[4][t] = __ldcg(f + 4);
        }
        __syncthreads();
#pragma unroll
        for (int s = RFIN / 2; s > 0; s >>= 1) {
            if (t < s) {
#pragma unroll
                for (int k = 0; k < 5; ++k)
                    red[k][t] += red[k][t + s];
            }
            __syncthreads();
        }

        if (t == 0) {
            float identity = red[0][0] / (float)NPTS;
            // counts were accumulated once per coord (3x per point) -> exact /3
            float nv = red[1][0] / 3.0f;
            float rs = red[2][0];
            float vs = red[3][0];
            float vc = red[4][0] / 3.0f;
            float recon    = (nv > 0.f) ? rs / fmaxf(nv, 1.f) : 0.f;
            float temporal = (vc > 0.f) ? vs / fmaxf(vc, 1.f) : 0.f;

            // adaptive re-weighting (faithful to reference)
            float rl = recon, tl = temporal, il = identity;
            bool  all_pos = (rl > 0.f) && (tl > 0.f) && (il > 0.f);
            float maxc    = fmaxf(rl, fmaxf(tl, il));
            float target  = maxc / 3.f;
            float thresh  = 10.f * target;
            float rw = (all_pos && rl > thresh) ? 1.0f * target / fmaxf(rl, 1e-30f) : 1.0f;
            float tw = (all_pos && tl > thresh) ? 0.5f * target / fmaxf(tl, 1e-30f) : 0.5f;
            float iw = (all_pos && il > thresh) ? 0.1f * target / fmaxf(il, 1e-30f) : 0.1f;

            out[0] = rw * recon + tw * temporal + iw * identity;
            out[1] = recon;
            out[2] = temporal;
            out[3] = identity;

            g_ctr = 0;   // self-reset for next graph replay
        }
    }
}

extern "C" void kernel_launch(void* const* d_in, const int* in_sizes, int n_in,
                              void* d_out, int out_size)
{
    const float* pred = (const float*)d_in[0];
    const float* gt   = (const float*)d_in[1];
    const float* vis  = (const float*)d_in[2];
    float* out = (float*)d_out;
    (void)in_sizes; (void)n_in; (void)out_size;

    main_k<<<NCTA, THREADS>>>(pred, gt, vis);      // 1536 blocks x 256
    finish_k<<<RFIN, 512>>>(out);                  // 128 blocks, fused tail
}

// round 8
// speedup vs baseline: 1.1274x; 1.1274x over previous
#include <cuda_runtime.h>

// Problem shape (fixed by the dataset reference)
#define BB      16
#define TT      256
#define NPTS    2048
#define NF      (NPTS * 3)             // 6144 flat (point,coord) indices
#define TCHUNK  32
#define NCHUNKS (TT / TCHUNK)          // 8
#define BC      (BB * NCHUNKS)         // 128 partial groups
#define THREADS 256
#define CPB     (NF / THREADS)         // 24 CTAs per bc group
#define NCTA    (BC * CPB)             // 3072 main CTAs
#define RFIN    256                    // finish CTAs
#define PTSPC   (NPTS / RFIN)          // 8 points per finish CTA
#define FLATSPC (PTSPC * 3)            // 24 flats per finish CTA
#define NGRP    16                     // bc groups in finish stage A
#define BCG     (BC / NGRP)            // 8 bc per group

// Partial per-(n,c) stats: g_part[bc][stat][flat], stat: 0 sxp, 1 ssp, 2 sxg, 3 ssg, 4 cnt
__device__ float  g_part[BC * 5 * NF];      // 15.7 MB, fully overwritten each replay
__device__ float4 g_pscal[NCTA];            // per-CTA: cnt3x, recon, vels, velc3x
__device__ float  g_fin[RFIN * 5];          // per-finish-CTA: id, cnt3x, recon, vels, velc3x
__device__ unsigned g_ctr;                  // last-block counter (self-resetting)

__global__ __launch_bounds__(THREADS) void main_k(
    const float* __restrict__ pred,
    const float* __restrict__ gt,
    const float* __restrict__ vis)
{
    const int bc    = blockIdx.x / CPB;
    const int sub   = blockIdx.x - bc * CPB;
    const int flat  = sub * THREADS + threadIdx.x;
    const int chunk = bc & (NCHUNKS - 1);
    const int b     = bc >> 3;                 // NCHUNKS = 8
    const int t0    = chunk * TCHUNK;

    const int   n = flat / 3;
    const int   c = flat - 3 * n;
    const float w = (c == 2) ? 2.f : 1.f;

    const int row0 = b * TT + t0;
    const float* pp = pred + (long)row0 * NF + flat;
    const float* gp = gt   + (long)row0 * NF + flat;
    const float* vp = vis  + (long)row0 * NPTS + n;

    float sxp = 0.f, ssp = 0.f, sxg = 0.f, ssg = 0.f, cnt = 0.f;
    float recon = 0.f, vels = 0.f, velc = 0.f;

    float pd = 0.f, pm = 0.f;
    if (t0 > 0) {
        pm = (vp[-NPTS] > 0.5f) ? 1.f : 0.f;
        pd = pp[-NF] - gp[-NF];
    }

#pragma unroll 4
    for (int t = 0; t < TCHUNK; ++t) {
        float m = (vp[0] > 0.5f) ? 1.f : 0.f;
        float p = pp[0];
        float g = gp[0];
        pp += NF; gp += NF; vp += NPTS;

        float d = p - g;
        recon += w * (m * d) * d;
        cnt   += m;

        float mp = m * p, mg = m * g;
        sxp += mp;  ssp += mp * p;
        sxg += mg;  ssg += mg * g;

        float vm = m * pm;
        float tv = d - pd;
        vels += (vm * tv) * tv;
        velc += vm;

        pd = d; pm = m;
    }

    // per-(n,c) stats -> partial buffer (coalesced scalar stores, no atomics)
    {
        float* out = &g_part[(long)bc * 5 * NF + flat];
        out[0 * NF] = sxp;
        out[1 * NF] = ssp;
        out[2 * NF] = sxg;
        out[3 * NF] = ssg;
        out[4 * NF] = cnt;
    }

    // scalar partials: warp reduce -> smem -> one float4 store per CTA
    const unsigned fmask = 0xffffffffu;
    __shared__ float swarp[8][4];
#pragma unroll
    for (int o = 16; o > 0; o >>= 1) {
        cnt   += __shfl_down_sync(fmask, cnt,   o);
        recon += __shfl_down_sync(fmask, recon, o);
        vels  += __shfl_down_sync(fmask, vels,  o);
        velc  += __shfl_down_sync(fmask, velc,  o);
    }
    int wd = threadIdx.x >> 5;
    if ((threadIdx.x & 31) == 0) {
        swarp[wd][0] = cnt; swarp[wd][1] = recon; swarp[wd][2] = vels; swarp[wd][3] = velc;
    }
    __syncthreads();
    if (threadIdx.x == 0) {
        float s0 = 0.f, s1 = 0.f, s2 = 0.f, s3 = 0.f;
#pragma unroll
        for (int i = 0; i < 8; ++i) {
            s0 += swarp[i][0]; s1 += swarp[i][1]; s2 += swarp[i][2]; s3 += swarp[i][3];
        }
        g_pscal[blockIdx.x] = make_float4(s0, s1, s2, s3);
    }
}

// Fused finish: float4 group-split reduce of partials, identity, scalar fold,
// last block combines and writes the 4 outputs.
__global__ __launch_bounds__(512) void finish_k(float* __restrict__ out)
{
    const int t  = threadIdx.x;
    const int bx = blockIdx.x;
    const int f0 = bx * FLATSPC;

    // sgrp[grp][stat][24 floats]; written as float4 per (stat,col)
    __shared__ float sgrp[NGRP][5][FLATSPC];
    __shared__ float scomb[5][FLATSPC];
    __shared__ float part5[5];
    __shared__ bool  islast;

    // Stage A: t -> grp = t/32 (16 groups), pair = t%32 (30 valid: stat=pair/6, col=pair%6)
    {
        int grp  = t >> 5;
        int pair = t & 31;
        if (pair < 30) {
            int stat = pair / 6;
            int col  = pair - stat * 6;
            const float* base = g_part + (long)(grp * BCG) * 5 * NF
                                       + (long)stat * NF + f0 + col * 4;
            float4 s = make_float4(0.f, 0.f, 0.f, 0.f);
#pragma unroll
            for (int i = 0; i < BCG; ++i) {
                float4 v = *(const float4*)(base + (long)i * 5 * NF);
                s.x += v.x; s.y += v.y; s.z += v.z; s.w += v.w;
            }
            *(float4*)&sgrp[grp][stat][col * 4] = s;
        }
    }
    __syncthreads();

    // Stage B1: combine groups (threads 0..119); Stage C: scalar fold (threads 128..159)
    if (t < 5 * FLATSPC) {
        int stat = t / FLATSPC;
        int fo   = t - stat * FLATSPC;
        float s = 0.f;
#pragma unroll
        for (int g = 0; g < NGRP; ++g)
            s += sgrp[g][stat][fo];
        scomb[stat][fo] = s;
    }
    if (t >= 128 && t < 160) {
        int lane = t - 128;                         // entries 0..11 valid
        float4 v = make_float4(0.f, 0.f, 0.f, 0.f);
        if (lane < NCTA / RFIN)                     // 12 main CTAs per finish CTA
            v = g_pscal[bx * (NCTA / RFIN) + lane];
#pragma unroll
        for (int o = 16; o > 0; o >>= 1) {
            v.x += __shfl_down_sync(0xffffffffu, v.x, o);
            v.y += __shfl_down_sync(0xffffffffu, v.y, o);
            v.z += __shfl_down_sync(0xffffffffu, v.z, o);
            v.w += __shfl_down_sync(0xffffffffu, v.w, o);
        }
        if (lane == 0) {
            part5[1] = v.x; part5[2] = v.y; part5[3] = v.z; part5[4] = v.w;
        }
    }
    __syncthreads();

    // Stage B2: identity for this CTA's 8 points (warp 0)
    float idp = 0.f;
    if (t < PTSPC) {
        int fo = t * 3;
        float cn = scomb[4][fo];
        if (cn > 1.f) {
            float inv_n  = 1.f / cn;
            float inv_n1 = 1.f / (cn - 1.f);
            float adsum = 0.f, vgsum = 0.f;
#pragma unroll
            for (int k = 0; k < 3; ++k) {
                float sp  = scomb[0][fo + k];
                float ssp = scomb[1][fo + k];
                float sg  = scomb[2][fo + k];
                float ssg = scomb[3][fo + k];
                float vp = (ssp - sp * sp * inv_n) * inv_n1;
                float vg = (ssg - sg * sg * inv_n) * inv_n1;
                adsum += fabsf(vp - vg);
                vgsum += vg;
            }
            idp = adsum / (vgsum + 1e-6f);
        }
    }
    if (t < 32) {
#pragma unroll
        for (int o = 16; o > 0; o >>= 1)
            idp += __shfl_down_sync(0xffffffffu, idp, o);
        if (t == 0) part5[0] = idp;
    }
    __syncthreads();

    if (t < 5) g_fin[bx * 5 + t] = part5[t];
    __threadfence();
    if (t == 0) {
        unsigned old = atomicAdd(&g_ctr, 1u);
        islast = (old == RFIN - 1);
    }
    __syncthreads();

    if (islast) {
        __threadfence();
        __shared__ float red[5][RFIN];
        if (t < RFIN) {                    // only t<256 touches red[]
            const float* f = &g_fin[t * 5];
            red[0][t] = __ldcg(f + 0);
            red[1][t] = __ldcg(f + 1);
            red[2][t] = __ldcg(f + 2);
            red[3][t] = __ldcg(f + 3);
            red[4][t] = __ldcg(f + 4);
        }
        __syncthreads();
#pragma unroll
        for (int s = RFIN / 2; s > 0; s >>= 1) {
            if (t < s) {
#pragma unroll
                for (int k = 0; k < 5; ++k)
                    red[k][t] += red[k][t + s];
            }
            __syncthreads();
        }

        if (t == 0) {
            float identity = red[0][0] / (float)NPTS;
            // counts were accumulated once per coord (3x per point) -> exact /3
            float nv = red[1][0] / 3.0f;
            float rs = red[2][0];
            float vs = red[3][0];
            float vc = red[4][0] / 3.0f;
            float recon    = (nv > 0.f) ? rs / fmaxf(nv, 1.f) : 0.f;
            float temporal = (vc > 0.f) ? vs / fmaxf(vc, 1.f) : 0.f;

            // adaptive re-weighting (faithful to reference)
            float rl = recon, tl = temporal, il = identity;
            bool  all_pos = (rl > 0.f) && (tl > 0.f) && (il > 0.f);
            float maxc    = fmaxf(rl, fmaxf(tl, il));
            float target  = maxc / 3.f;
            float thresh  = 10.f * target;
            float rw = (all_pos && rl > thresh) ? 1.0f * target / fmaxf(rl, 1e-30f) : 1.0f;
            float tw = (all_pos && tl > thresh) ? 0.5f * target / fmaxf(tl, 1e-30f) : 0.5f;
            float iw = (all_pos && il > thresh) ? 0.1f * target / fmaxf(il, 1e-30f) : 0.1f;

            out[0] = rw * recon + tw * temporal + iw * identity;
            out[1] = recon;
            out[2] = temporal;
            out[3] = identity;

            g_ctr = 0;   // self-reset for next graph replay
        }
    }
}

extern "C" void kernel_launch(void* const* d_in, const int* in_sizes, int n_in,
                              void* d_out, int out_size)
{
    const float* pred = (const float*)d_in[0];
    const float* gt   = (const float*)d_in[1];
    const float* vis  = (const float*)d_in[2];
    float* out = (float*)d_out;
    (void)in_sizes; (void)n_in; (void)out_size;

    main_k<<<NCTA, THREADS>>>(pred, gt, vis);      // 3072 blocks x 256
    finish_k<<<RFIN, 512>>>(out);                  // 256 blocks, fused tail
}